// round 1
// baseline (speedup 1.0000x reference)
#include <cuda_runtime.h>
#include <math.h>

// Problem constants (fixed by setup_inputs)
#define BATCH 16
#define HH 1024
#define WW 1024
#define NPIX (HH*WW)
#define NTOT (BATCH*NPIX)

// Scratch (allocation-free: __device__ globals)
__device__ int g_parP[NTOT];
__device__ int g_parT[NTOT];
__device__ unsigned char g_fg[NTOT];     // bit0: pred>0.5, bit1: target>0
__device__ unsigned char g_flagP[NTOT];  // component-of-pred contains a mistake
__device__ unsigned char g_flagT[NTOT];  // component-of-target contains a mistake
__device__ double g_sum;

// ---------------------------------------------------------------------------
// init: foreground bits, parent = self, flags = 0, sum = 0
// ---------------------------------------------------------------------------
__global__ void k_init(const float* __restrict__ preds,
                       const float* __restrict__ targs) {
    int i = blockIdx.x * blockDim.x + threadIdx.x;   // vec4 index
    int base = i << 2;
    if (base >= NTOT) return;
    float4 p = reinterpret_cast<const float4*>(preds)[i];
    float4 t = reinterpret_cast<const float4*>(targs)[i];
    uchar4 fg;
    fg.x = (p.x > 0.5f ? 1 : 0) | (t.x > 0.0f ? 2 : 0);
    fg.y = (p.y > 0.5f ? 1 : 0) | (t.y > 0.0f ? 2 : 0);
    fg.z = (p.z > 0.5f ? 1 : 0) | (t.z > 0.0f ? 2 : 0);
    fg.w = (p.w > 0.5f ? 1 : 0) | (t.w > 0.0f ? 2 : 0);
    reinterpret_cast<uchar4*>(g_fg)[i] = fg;
    int4 par = make_int4(base, base + 1, base + 2, base + 3);
    reinterpret_cast<int4*>(g_parP)[i] = par;
    reinterpret_cast<int4*>(g_parT)[i] = par;
    reinterpret_cast<uchar4*>(g_flagP)[i] = make_uchar4(0, 0, 0, 0);
    reinterpret_cast<uchar4*>(g_flagT)[i] = make_uchar4(0, 0, 0, 0);
    if (i == 0) g_sum = 0.0;
}

// ---------------------------------------------------------------------------
// union-find primitives (atomicMin union; volatile reads during merge phase)
// ---------------------------------------------------------------------------
__device__ __forceinline__ int find_root_v(int* par, int l) {
    int p = *((volatile int*)&par[l]);
    while (p != l) { l = p; p = *((volatile int*)&par[l]); }
    return l;
}

__device__ __forceinline__ void unite(int* par, int a, int b) {
    while (true) {
        a = find_root_v(par, a);
        b = find_root_v(par, b);
        if (a == b) return;
        if (a < b) { int t = a; a = b; b = t; }   // a > b: link a -> b
        int old = atomicMin(&par[a], b);
        if (old == a) return;                     // we installed the link
        a = old;                                  // lost race: merge old with b
    }
}

// ---------------------------------------------------------------------------
// merge: union with left / up neighbors (4-connectivity, per image)
// ---------------------------------------------------------------------------
__global__ void k_merge() {
    int i = blockIdx.x * blockDim.x + threadIdx.x;
    if (i >= NTOT) return;
    unsigned char f = g_fg[i];
    if (!f) return;
    int x = i & (WW - 1);
    int row = i >> 10;                 // global row (W = 1024)
    int yin = row & (HH - 1);          // row within image
    bool hasL = (x > 0);
    bool hasU = (yin > 0);
    unsigned char fl = hasL ? g_fg[i - 1] : 0;
    unsigned char fu = hasU ? g_fg[i - WW] : 0;
    if (f & 1) {
        if (fl & 1) unite(g_parP, i, i - 1);
        if (fu & 1) unite(g_parP, i, i - WW);
    }
    if (f & 2) {
        if (fl & 2) unite(g_parT, i, i - 1);
        if (fu & 2) unite(g_parT, i, i - WW);
    }
}

// ---------------------------------------------------------------------------
// compress + flag: par[i] <- root; mistake pixels set flag[root] = 1
// ---------------------------------------------------------------------------
__global__ void k_compress_flag() {
    int i = blockIdx.x * blockDim.x + threadIdx.x;
    if (i >= NTOT) return;
    unsigned char f = g_fg[i];
    if (!f) return;
    if (f & 1) {
        int r = find_root_v(g_parP, i);
        g_parP[i] = r;
        if (!(f & 2)) g_flagP[r] = 1;   // pred-fg pixel where target-bg => mistake
    }
    if (f & 2) {
        int r = find_root_v(g_parT, i);
        g_parT[i] = r;
        if (!(f & 1)) g_flagT[r] = 1;   // target-fg pixel where pred-bg => mistake
    }
}

// ---------------------------------------------------------------------------
// final: fused BCE-with-logits loss * weight, block reduce, atomicAdd(double)
// weight = 0.5 + 0.25 * neg + 0.25 * pos
// ---------------------------------------------------------------------------
__global__ void k_final(const float* __restrict__ preds,
                        const float* __restrict__ targs) {
    int i = blockIdx.x * blockDim.x + threadIdx.x;   // vec4 index
    int base = i << 2;
    float local = 0.0f;
    if (base < NTOT) {
        float4 p4 = reinterpret_cast<const float4*>(preds)[i];
        float4 t4 = reinterpret_cast<const float4*>(targs)[i];
        uchar4 f4 = reinterpret_cast<const uchar4*>(g_fg)[i];
        float pv[4] = {p4.x, p4.y, p4.z, p4.w};
        float tv[4] = {t4.x, t4.y, t4.z, t4.w};
        unsigned char fv[4] = {f4.x, f4.y, f4.z, f4.w};
#pragma unroll
        for (int j = 0; j < 4; j++) {
            int idx = base + j;
            float p = pv[j];
            float t = tv[j];
            float loss = fmaxf(p, 0.0f) - p * t + log1pf(expf(-fabsf(p)));
            float w = 0.5f;
            unsigned char f = fv[j];
            if (f & 2) w += 0.25f * (float)g_flagT[g_parT[idx]];
            if (f & 1) w += 0.25f * (float)g_flagP[g_parP[idx]];
            local += w * loss;
        }
    }
    // warp reduce
#pragma unroll
    for (int off = 16; off > 0; off >>= 1)
        local += __shfl_down_sync(0xffffffffu, local, off);
    __shared__ float ssum[8];
    int lane = threadIdx.x & 31;
    int warp = threadIdx.x >> 5;
    if (lane == 0) ssum[warp] = local;
    __syncthreads();
    if (warp == 0) {
        float v = (lane < (blockDim.x >> 5)) ? ssum[lane] : 0.0f;
#pragma unroll
        for (int off = 4; off > 0; off >>= 1)
            v += __shfl_down_sync(0xffffffffu, v, off);
        if (lane == 0) atomicAdd(&g_sum, (double)v);
    }
}

__global__ void k_out(float* __restrict__ out) {
    out[0] = (float)(g_sum / (double)NTOT);
}

// ---------------------------------------------------------------------------
extern "C" void kernel_launch(void* const* d_in, const int* in_sizes, int n_in,
                              void* d_out, int out_size) {
    const float* preds = (const float*)d_in[0];
    const float* targs = (const float*)d_in[1];
    float* out = (float*)d_out;

    const int TPB = 256;
    k_init<<<(NTOT / 4 + TPB - 1) / TPB, TPB>>>(preds, targs);
    k_merge<<<(NTOT + TPB - 1) / TPB, TPB>>>();
    k_compress_flag<<<(NTOT + TPB - 1) / TPB, TPB>>>();
    k_final<<<(NTOT / 4 + TPB - 1) / TPB, TPB>>>(preds, targs);
    k_out<<<1, 1>>>(out);
}